// round 3
// baseline (speedup 1.0000x reference)
#include <cuda_runtime.h>
#include <cstdint>

#define S 8192
#define H 1024
#define NSM 128
#define SCAN_THREADS 512
#define NREP 8
#define REP_STRIDE 64   // ints between replicas (256B -> distinct L2 slices)

// Scratch: input-side gate projections gx[S][3H] and per-step flag replicas.
__device__ float g_gx[(size_t)S * 3 * H];
// flags[(t*4 + chunk)*NREP + rep] * REP_STRIDE, counted to 32 per chunk group
__device__ unsigned int g_flags[(size_t)S * 4 * NREP * REP_STRIDE];

// ---------------------------------------------------------------------------
// packed fp32x2 helpers (sm_103a FFMA2 path)
// ---------------------------------------------------------------------------
__device__ __forceinline__ unsigned long long pack2(float lo, float hi) {
    unsigned long long r;
    asm("mov.b64 %0, {%1, %2};" : "=l"(r) : "f"(lo), "f"(hi));
    return r;
}
__device__ __forceinline__ unsigned long long ffma2(unsigned long long a,
                                                    unsigned long long b,
                                                    unsigned long long c) {
    unsigned long long d;
    asm("fma.rn.f32x2 %0, %1, %2, %3;" : "=l"(d) : "l"(a), "l"(b), "l"(c));
    return d;
}
__device__ __forceinline__ float hsum2(unsigned long long a) {
    float lo, hi;
    asm("mov.b64 {%0, %1}, %2;" : "=f"(lo), "=f"(hi) : "l"(a));
    return lo + hi;
}

// ---------------------------------------------------------------------------
// Kernel 1: gx = inp @ W_ih^T + b_ih  (fp32 GEMM, 128x128x16 tiles, FFMA2)
// Also clears the flag array so each graph replay starts clean.
// ---------------------------------------------------------------------------
__global__ __launch_bounds__(256) void gemm_gx_kernel(
    const float* __restrict__ A,
    const float* __restrict__ Wih,
    const float* __restrict__ bih)
{
    __shared__ __align__(16) float As[16][132];
    __shared__ __align__(16) float Bs[16][132];

    const int tid = threadIdx.x;
    const int flat_bid = blockIdx.y * gridDim.x + blockIdx.x;

    // grid-stride clear of the flag array (uint4 stores)
    {
        const size_t nvec = ((size_t)S * 4 * NREP * REP_STRIDE) / 4;
        const size_t nthr = (size_t)gridDim.x * gridDim.y * 256;
        uint4 zero = make_uint4(0u, 0u, 0u, 0u);
        for (size_t i = (size_t)flat_bid * 256 + tid; i < nvec; i += nthr)
            ((uint4*)g_flags)[i] = zero;
    }

    const int m0 = blockIdx.y * 128;
    const int n0 = blockIdx.x * 128;
    const int tx = tid & 15;
    const int ty = tid >> 4;

    unsigned long long acc2[8][4];
#pragma unroll
    for (int i = 0; i < 8; ++i)
#pragma unroll
        for (int q = 0; q < 4; ++q) acc2[i][q] = 0ULL;

    for (int kt = 0; kt < 1024; kt += 16) {
#pragma unroll
        for (int r = 0; r < 2; ++r) {
            int idx = tid + r * 256;
            int row = idx >> 2;
            int kq  = idx & 3;
            float4 v = *(const float4*)(A + (size_t)(m0 + row) * 1024 + kt + kq * 4);
            As[kq * 4 + 0][row] = v.x;
            As[kq * 4 + 1][row] = v.y;
            As[kq * 4 + 2][row] = v.z;
            As[kq * 4 + 3][row] = v.w;
        }
#pragma unroll
        for (int r = 0; r < 2; ++r) {
            int idx = tid + r * 256;
            int n  = idx >> 2;
            int kq = idx & 3;
            float4 v = *(const float4*)(Wih + (size_t)(n0 + n) * 1024 + kt + kq * 4);
            Bs[kq * 4 + 0][n] = v.x;
            Bs[kq * 4 + 1][n] = v.y;
            Bs[kq * 4 + 2][n] = v.z;
            Bs[kq * 4 + 3][n] = v.w;
        }
        __syncthreads();

#pragma unroll
        for (int k = 0; k < 16; ++k) {
            float4 b0 = *(const float4*)&Bs[k][tx * 8];
            float4 b1 = *(const float4*)&Bs[k][tx * 8 + 4];
            unsigned long long rb2[4];
            rb2[0] = pack2(b0.x, b0.y);
            rb2[1] = pack2(b0.z, b0.w);
            rb2[2] = pack2(b1.x, b1.y);
            rb2[3] = pack2(b1.z, b1.w);
#pragma unroll
            for (int i = 0; i < 8; ++i) {
                float a = As[k][ty * 8 + i];
                unsigned long long a2 = pack2(a, a);
#pragma unroll
                for (int q = 0; q < 4; ++q)
                    acc2[i][q] = ffma2(a2, rb2[q], acc2[i][q]);
            }
        }
        __syncthreads();
    }

#pragma unroll
    for (int i = 0; i < 8; ++i) {
        size_t rowoff = (size_t)(m0 + ty * 8 + i) * 3072 + n0 + tx * 8;
#pragma unroll
        for (int jq = 0; jq < 2; ++jq) {
            float lo0, hi0, lo1, hi1;
            asm("mov.b64 {%0, %1}, %2;" : "=f"(lo0), "=f"(hi0) : "l"(acc2[i][jq * 2 + 0]));
            asm("mov.b64 {%0, %1}, %2;" : "=f"(lo1), "=f"(hi1) : "l"(acc2[i][jq * 2 + 1]));
            float4 v;
            v.x = lo0 + bih[n0 + tx * 8 + jq * 4 + 0];
            v.y = hi0 + bih[n0 + tx * 8 + jq * 4 + 1];
            v.z = lo1 + bih[n0 + tx * 8 + jq * 4 + 2];
            v.w = hi1 + bih[n0 + tx * 8 + jq * 4 + 3];
            *(float4*)(g_gx + rowoff + jq * 4) = v;
        }
    }
}

// ---------------------------------------------------------------------------
// Kernel 2: persistent GRU scan. 128 CTAs (one per SM, single wave),
// 512 threads each. Each CTA owns 8 output dims => 24 gate-rows of W_hh,
// register-resident as packed f32x2. h_t lives in d_out (L2 exchange).
// Sync: per-k-chunk group flags (4 groups of 32 producer CTAs), 8 replicas
// each, publishers use red.release, each consumer WARP polls its replica
// directly -> no CTA barrier on the wake path.
// ---------------------------------------------------------------------------
__global__ __launch_bounds__(SCAN_THREADS, 1) void gru_scan_kernel(
    const float* __restrict__ Whh,
    const float* __restrict__ bhh,
    float* __restrict__ out)
{
    const int tid  = threadIdx.x;
    const int warp = tid >> 5;
    const int lane = tid & 31;
    const int c = warp & 3;        // k-chunk id (0..3)
    const int g = warp >> 2;       // row-group id (0..3)
    const int bid = blockIdx.x;
    const int obase = bid * 8;
    const int k0 = c * 256 + lane * 8;
    const int gb  = bid >> 5;              // producer chunk group of this CTA
    const int rep = (bid + warp) & (NREP - 1);

    __shared__ __align__(16) float partials[24][36];

    // --- preload 6 gate-rows x 8 cols of W_hh, packed as f32x2 ---
    unsigned long long w2[6][4];
#pragma unroll
    for (int j = 0; j < 6; ++j) {
        int gr  = g * 6 + j;                          // 0..23
        int row = (gr >> 3) * H + obase + (gr & 7);   // gate*H + output index
        const float4* p = (const float4*)(Whh + (size_t)row * H + k0);
        float4 a = p[0], b = p[1];
        w2[j][0] = pack2(a.x, a.y);
        w2[j][1] = pack2(a.z, a.w);
        w2[j][2] = pack2(b.x, b.y);
        w2[j][3] = pack2(b.z, b.w);
    }

    const bool isw0 = (warp == 0);
    const int gate = lane >> 3;   // 0=r, 1=z, 2=n (lanes < 24)
    const int o    = lane & 7;
    float bh = 0.f;
    if (isw0 && lane < 24) bh = bhh[gate * H + obase + o];
    float hprev = 0.f;            // lanes 0..7 carry h for their output dim

    const size_t gx_lane_off = (size_t)gate * H + obase + o;

    for (int t = 0; t < S; ++t) {
        // prefetch gx for this step (independent of the flag)
        float gxv = 0.f;
        if (isw0 && lane < 24)
            gxv = g_gx[(size_t)t * (3 * H) + gx_lane_off];

        unsigned long long h2[4];
        if (t == 0) {
#pragma unroll
            for (int q = 0; q < 4; ++q) h2[q] = 0ULL;
        } else {
            // per-warp wait: chunk c of h_{t-1} published by its 32 CTAs
            if (lane == 0) {
                const unsigned int* fp =
                    &g_flags[(((size_t)(t - 1) * 4 + c) * NREP + rep) * REP_STRIDE];
                unsigned int v;
                do {
                    asm volatile("ld.acquire.gpu.global.u32 %0, [%1];"
                                 : "=r"(v) : "l"(fp) : "memory");
                } while (v < 32u);
            }
            __syncwarp();
            const float4* hp = (const float4*)(out + (size_t)(t - 1) * H + k0);
            float4 a = hp[0], b = hp[1];
            h2[0] = pack2(a.x, a.y);
            h2[1] = pack2(a.z, a.w);
            h2[2] = pack2(b.x, b.y);
            h2[3] = pack2(b.z, b.w);
        }

        // --- packed partial dots: 6 rows x 4 f32x2 FMAs ---
        float accv[6];
#pragma unroll
        for (int j = 0; j < 6; ++j) {
            unsigned long long acc = 0ULL;
#pragma unroll
            for (int q = 0; q < 4; ++q) acc = ffma2(w2[j][q], h2[q], acc);
            accv[j] = hsum2(acc);
        }

        // --- 2 shuffle rounds: 32 lanes -> 8 representatives ---
#pragma unroll
        for (int j = 0; j < 6; ++j) {
            accv[j] += __shfl_xor_sync(0xFFFFFFFFu, accv[j], 16);
            accv[j] += __shfl_xor_sync(0xFFFFFFFFu, accv[j], 8);
        }
        if (lane < 8) {
#pragma unroll
            for (int j = 0; j < 6; ++j)
                partials[g * 6 + j][c * 8 + lane] = accv[j];
        }
        __syncthreads();   // bar1: partials ready for finalize

        // --- finalize: warp 0, one lane per gate-row (24 lanes) ---
        if (isw0) {
            float val = 0.f;
            if (lane < 24) {
                const float4* pr = (const float4*)(&partials[lane][0]);
                float4 p0 = pr[0], p1 = pr[1], p2 = pr[2], p3 = pr[3];
                float4 p4 = pr[4], p5 = pr[5], p6 = pr[6], p7 = pr[7];
                float4 q0, q1, q2, q3, r0, r1, f;
                q0.x = p0.x + p1.x; q0.y = p0.y + p1.y; q0.z = p0.z + p1.z; q0.w = p0.w + p1.w;
                q1.x = p2.x + p3.x; q1.y = p2.y + p3.y; q1.z = p2.z + p3.z; q1.w = p2.w + p3.w;
                q2.x = p4.x + p5.x; q2.y = p4.y + p5.y; q2.z = p4.z + p5.z; q2.w = p4.w + p5.w;
                q3.x = p6.x + p7.x; q3.y = p6.y + p7.y; q3.z = p6.z + p7.z; q3.w = p6.w + p7.w;
                r0.x = q0.x + q1.x; r0.y = q0.y + q1.y; r0.z = q0.z + q1.z; r0.w = q0.w + q1.w;
                r1.x = q2.x + q3.x; r1.y = q2.y + q3.y; r1.z = q2.z + q3.z; r1.w = q2.w + q3.w;
                f.x = r0.x + r1.x; f.y = r0.y + r1.y; f.z = r0.z + r1.z; f.w = r0.w + r1.w;
                float s = bh + ((f.x + f.y) + (f.z + f.w));
                // r/z rows fold gx in; n rows keep hidden side separate
                val = (lane < 16) ? (s + gxv) : s;
            }
            float v_z  = __shfl_sync(0xFFFFFFFFu, val, o + 8);
            float v_n  = __shfl_sync(0xFFFFFFFFu, val, o + 16);
            float gx_n = __shfl_sync(0xFFFFFFFFu, gxv, o + 16);
            if (lane < 8) {
                float er = __expf(-val);
                float r  = __fdividef(1.f, 1.f + er);
                float ez = __expf(-v_z);
                float z  = __fdividef(1.f, 1.f + ez);
                float a  = gx_n + r * v_n;
                float e2 = __expf(2.f * a);
                float n  = 1.f - __fdividef(2.f, e2 + 1.f);   // tanh(a)
                float hn = z * (hprev - n) + n;               // (1-z)*n + z*h
                hprev = hn;
                out[(size_t)t * H + obase + o] = hn;
            }
            __syncwarp();   // order STGs before the release reds below
            if (lane < NREP) {
                unsigned int* fp =
                    &g_flags[(((size_t)t * 4 + gb) * NREP + lane) * REP_STRIDE];
                asm volatile("red.release.gpu.global.add.u32 [%0], 1;"
                             :: "l"(fp) : "memory");
            }
        }
        __syncthreads();   // bar2: finalize done before partials overwrite
    }
}

// ---------------------------------------------------------------------------
extern "C" void kernel_launch(void* const* d_in, const int* in_sizes, int n_in,
                              void* d_out, int out_size)
{
    const float* inp  = (const float*)d_in[0];  // [8192, 1024]
    const float* W_ih = (const float*)d_in[1];  // [3072, 1024]
    const float* W_hh = (const float*)d_in[2];  // [3072, 1024]
    const float* b_ih = (const float*)d_in[3];  // [3072]
    const float* b_hh = (const float*)d_in[4];  // [3072]
    float* out = (float*)d_out;                 // [8192, 1024]

    // 1) gx = inp @ W_ih^T + b_ih (also clears g_flags for this replay)
    dim3 ggrid(3072 / 128, S / 128);
    gemm_gx_kernel<<<ggrid, 256>>>(inp, W_ih, b_ih);

    // 2) persistent sequential GRU scan (one wave of 128 CTAs)
    gru_scan_kernel<<<NSM, SCAN_THREADS>>>(W_hh, b_hh, out);
}